// round 15
// baseline (speedup 1.0000x reference)
#include <cuda_runtime.h>

#define N_ATOMS 4096
#define N_PAIRS 4000000
#define N_CELLS (N_ATOMS * N_ATOMS)
#define R_REP 16
#define PAIR_THREADS 256
#define PAIR_BLOCKS 888            // 6 CTAs/SM x 148 SMs: exactly resident
#define N_QUADS (N_PAIRS / 4)
#define CUT_CODE 5462u   // code >= 5462  <=>  inv_d >= 1/12  <=>  d <= 12

// Persistent __device__ scratch (static; zero at module load).
__device__ float          g_scratch[R_REP * N_ATOMS * 4]; // replicated force accum (~1 MB)
__device__ float          g_energy;
__device__ unsigned short g_dcode[N_CELLS];               // u16 inv-codes (32 MB, L2-resident)

// ---------- 1) quantize dist -> u16 inv-codes (streaming, ~96 MB) ----------
__global__ void __launch_bounds__(256) convert_kernel(const float4* __restrict__ dist4) {
    int tid = blockIdx.x * blockDim.x + threadIdx.x;
    int stride = gridDim.x * blockDim.x;
    ushort4* dst = reinterpret_cast<ushort4*>(g_dcode);
    const int n4 = N_CELLS / 4;
    for (int i = tid; i < n4; i += stride) {
        float4 v = __ldcs(&dist4[i]);
        ushort4 c;
        c.x = (unsigned short)__float2uint_rn(65535.0f / v.x);
        c.y = (unsigned short)__float2uint_rn(65535.0f / v.y);
        c.z = (unsigned short)__float2uint_rn(65535.0f / v.z);
        c.w = (unsigned short)__float2uint_rn(65535.0f / v.w);
        dst[i] = c;
    }
}

__device__ __forceinline__ void do_pair(unsigned int code, float B, unsigned int ofs,
                                        const float* __restrict__ vector_mat,
                                        float* __restrict__ rep,
                                        int a, int b, float& esum) {
    if (code >= CUT_CODE) {
        float inv  = (float)code * (1.0f / 65535.0f);
        float inv2 = inv * inv;
        float inv6 = inv2 * inv2 * inv2;
        float e = B * inv6;
        esum += e;
        float f = -6.0f * e * inv;

        // 12B vec read via one aligned 16B load (50% of offsets), else one
        // extra small load. Default caching: cross-replay L2 reuse for vec.
        unsigned int byte = ofs * 12u;
        const char* base = (const char*)vector_mat + (byte & ~15u);
        float4 q = __ldg((const float4*)base);
        unsigned int o = byte & 15u;
        float vx, vy, vz;
        if (o == 0u)      { vx = q.x; vy = q.y; vz = q.z; }
        else if (o == 4u) { vx = q.y; vy = q.z; vz = q.w; }
        else if (o == 8u) {
            vx = q.z; vy = q.w;
            vz = __ldg((const float*)(base + 16));
        } else {            // o == 12
            float2 t = __ldg((const float2*)(base + 16));
            vx = q.w; vy = t.x; vz = t.y;
        }

        float fx = f * vx, fy = f * vy, fz = f * vz;

        float* pa = rep + a * 4;
        float* pb = rep + b * 4;
        asm volatile("red.global.add.v4.f32 [%0], {%1,%2,%3,%4};"
                     :: "l"(pa), "f"(fx), "f"(fy), "f"(fz), "f"(0.0f) : "memory");
        asm volatile("red.global.add.v4.f32 [%0], {%1,%2,%3,%4};"
                     :: "l"(pb), "f"(-fx), "f"(-fy), "f"(-fz), "f"(0.0f) : "memory");
    }
}

// ---------- 2) pair pass: u16 code gathers (L2-resident) + vec gathers ----------
__global__ void __launch_bounds__(PAIR_THREADS) pair_kernel(
    const float* __restrict__ vector_mat,
    const float* __restrict__ bcoef,
    const int4*  __restrict__ coord_idx4)   // 2 pairs per int4
{
    int tid = blockIdx.x * blockDim.x + threadIdx.x;
    int stride = gridDim.x * blockDim.x;
    float* rep = g_scratch + (size_t)(blockIdx.x % R_REP) * (N_ATOMS * 4);

    float esum = 0.0f;

    for (int i = tid; i < N_QUADS; i += stride) {
        int4 c01 = __ldcs(&coord_idx4[2 * i + 0]);
        int4 c23 = __ldcs(&coord_idx4[2 * i + 1]);
        float4 B = __ldcs((const float4*)bcoef + i);

        unsigned int o0 = ((unsigned int)c01.x << 12) | (unsigned int)c01.y;
        unsigned int o1 = ((unsigned int)c01.z << 12) | (unsigned int)c01.w;
        unsigned int o2 = ((unsigned int)c23.x << 12) | (unsigned int)c23.y;
        unsigned int o3 = ((unsigned int)c23.z << 12) | (unsigned int)c23.w;

        unsigned int k0 = __ldg(&g_dcode[o0]);
        unsigned int k1 = __ldg(&g_dcode[o1]);
        unsigned int k2 = __ldg(&g_dcode[o2]);
        unsigned int k3 = __ldg(&g_dcode[o3]);

        do_pair(k0, B.x, o0, vector_mat, rep, c01.x, c01.y, esum);
        do_pair(k1, B.y, o1, vector_mat, rep, c01.z, c01.w, esum);
        do_pair(k2, B.z, o2, vector_mat, rep, c23.x, c23.y, esum);
        do_pair(k3, B.w, o3, vector_mat, rep, c23.z, c23.w, esum);
    }

    // Energy: warp reduce -> block reduce -> one atomic per block.
    #pragma unroll
    for (int o = 16; o > 0; o >>= 1)
        esum += __shfl_xor_sync(0xffffffffu, esum, o);

    __shared__ float warp_s[PAIR_THREADS / 32];
    int lane = threadIdx.x & 31;
    int wid  = threadIdx.x >> 5;
    if (lane == 0) warp_s[wid] = esum;
    __syncthreads();
    if (wid == 0) {
        float v = (lane < (PAIR_THREADS / 32)) ? warp_s[lane] : 0.0f;
        #pragma unroll
        for (int o = 16; o > 0; o >>= 1)
            v += __shfl_xor_sync(0xffffffffu, v, o);
        if (lane == 0) atomicAdd(&g_energy, v);
    }
}

// ---------- 3) fold replicas, emit output, re-zero for next replay ----------
__global__ void __launch_bounds__(256) reduce_kernel(const float* __restrict__ forces_in,
                                                     float* __restrict__ d_out) {
    int idx = blockIdx.x * blockDim.x + threadIdx.x;   // 0 .. 4*N_ATOMS-1
    int a  = idx >> 2;
    int rs = idx & 3;

    float fx = 0.0f, fy = 0.0f, fz = 0.0f;
    #pragma unroll
    for (int k = 0; k < R_REP / 4; k++) {
        int r = rs + k * 4;
        float4* p = reinterpret_cast<float4*>(g_scratch + ((size_t)r * N_ATOMS + a) * 4);
        const float4 v = *p;
        fx += v.x; fy += v.y; fz += v.z;
        *p = make_float4(0.0f, 0.0f, 0.0f, 0.0f);
    }

    fx += __shfl_xor_sync(0xffffffffu, fx, 1);
    fy += __shfl_xor_sync(0xffffffffu, fy, 1);
    fz += __shfl_xor_sync(0xffffffffu, fz, 1);
    fx += __shfl_xor_sync(0xffffffffu, fx, 2);
    fy += __shfl_xor_sync(0xffffffffu, fy, 2);
    fz += __shfl_xor_sync(0xffffffffu, fz, 2);

    if (rs == 0) {
        d_out[1 + a * 3 + 0] = forces_in[a * 3 + 0] + fx;
        d_out[1 + a * 3 + 1] = forces_in[a * 3 + 1] + fy;
        d_out[1 + a * 3 + 2] = forces_in[a * 3 + 2] + fz;
    }
    if (idx == 0) {
        d_out[0] = g_energy;
        g_energy = 0.0f;
    }
}

extern "C" void kernel_launch(void* const* d_in, const int* in_sizes, int n_in,
                              void* d_out, int out_size) {
    const float4* dist4      = (const float4*)d_in[0];  // (4096, 4096) f32
    const float*  vector_mat = (const float*)d_in[1];   // (4096, 4096, 3) f32
    const float*  forces_in  = (const float*)d_in[2];   // (4096, 3) f32 zeros
    const float*  bcoef      = (const float*)d_in[3];   // (N_PAIRS,) f32
    const int4*   coord_idx4 = (const int4*)d_in[4];    // (N_PAIRS, 2) i32

    float* out = (float*)d_out;                         // [energy, forces(4096*3)]

    convert_kernel<<<1184, 256>>>(dist4);
    pair_kernel   <<<PAIR_BLOCKS, PAIR_THREADS>>>(vector_mat, bcoef, coord_idx4);
    reduce_kernel <<<(4 * N_ATOMS) / 256, 256>>>(forces_in, out);
}

// round 16
// speedup vs baseline: 1.0682x; 1.0682x over previous
#include <cuda_runtime.h>

#define N_ATOMS 4096
#define N_PAIRS 4000000
#define N_CELLS (N_ATOMS * N_ATOMS)
#define R_REP 16
#define PAIR_THREADS 256
#define PAIR_BLOCKS 1184
#define N_QUADS (N_PAIRS / 4)
#define CUT_CODE 5462u   // code >= 5462  <=>  inv_d >= 1/12  <=>  d <= 12

// Persistent __device__ scratch (static; zero at module load).
__device__ float          g_scratch[R_REP * N_ATOMS * 4]; // replicated force accum (~1 MB)
__device__ float          g_energy;
__device__ unsigned short g_dcode[N_CELLS];               // u16 inv-codes (32 MB, L2-resident)

// ---------- 1) quantize dist -> u16 inv-codes (streaming, ~96 MB) ----------
__global__ void __launch_bounds__(256) convert_kernel(const float4* __restrict__ dist4) {
    int tid = blockIdx.x * blockDim.x + threadIdx.x;
    int stride = gridDim.x * blockDim.x;
    ushort4* dst = reinterpret_cast<ushort4*>(g_dcode);
    const int n4 = N_CELLS / 4;
    for (int i = tid; i < n4; i += stride) {
        float4 v = __ldcs(&dist4[i]);
        // Fast reciprocal (MUFU.RCP + mul): |err| <= 1 code ulp, far below the
        // u16 quantization error already accepted.
        ushort4 c;
        c.x = (unsigned short)__float2uint_rn(__fdividef(65535.0f, v.x));
        c.y = (unsigned short)__float2uint_rn(__fdividef(65535.0f, v.y));
        c.z = (unsigned short)__float2uint_rn(__fdividef(65535.0f, v.z));
        c.w = (unsigned short)__float2uint_rn(__fdividef(65535.0f, v.w));
        dst[i] = c;
    }
}

__device__ __forceinline__ void do_pair(unsigned int code, float B, unsigned int ofs,
                                        const float* __restrict__ vector_mat,
                                        float* __restrict__ rep,
                                        int a, int b, float& esum) {
    if (code >= CUT_CODE) {
        float inv  = (float)code * (1.0f / 65535.0f);
        float inv2 = inv * inv;
        float inv6 = inv2 * inv2 * inv2;
        float e = B * inv6;
        esum += e;
        float f = -6.0f * e * inv;

        // 12B vec read via one aligned 16B evict-first load (50% of offsets),
        // else one extra small load. Evict-first protects the L2-resident codes
        // (R15 showed default caching evicts them and costs ~4 us).
        unsigned int byte = ofs * 12u;
        const char* base = (const char*)vector_mat + (byte & ~15u);
        float4 q = __ldcs((const float4*)base);
        unsigned int o = byte & 15u;
        float vx, vy, vz;
        if (o == 0u)      { vx = q.x; vy = q.y; vz = q.z; }
        else if (o == 4u) { vx = q.y; vy = q.z; vz = q.w; }
        else if (o == 8u) {
            vx = q.z; vy = q.w;
            vz = __ldcs((const float*)(base + 16));
        } else {            // o == 12
            float2 t = __ldcs((const float2*)(base + 16));
            vx = q.w; vy = t.x; vz = t.y;
        }

        float fx = f * vx, fy = f * vy, fz = f * vz;

        float* pa = rep + a * 4;
        float* pb = rep + b * 4;
        asm volatile("red.global.add.v4.f32 [%0], {%1,%2,%3,%4};"
                     :: "l"(pa), "f"(fx), "f"(fy), "f"(fz), "f"(0.0f) : "memory");
        asm volatile("red.global.add.v4.f32 [%0], {%1,%2,%3,%4};"
                     :: "l"(pb), "f"(-fx), "f"(-fy), "f"(-fz), "f"(0.0f) : "memory");
    }
}

// ---------- 2) pair pass: u16 code gathers (L2-resident) + vec gathers ----------
__global__ void __launch_bounds__(PAIR_THREADS) pair_kernel(
    const float* __restrict__ vector_mat,
    const float* __restrict__ bcoef,
    const int4*  __restrict__ coord_idx4)   // 2 pairs per int4
{
    int tid = blockIdx.x * blockDim.x + threadIdx.x;
    int stride = gridDim.x * blockDim.x;
    float* rep = g_scratch + (size_t)(blockIdx.x % R_REP) * (N_ATOMS * 4);

    float esum = 0.0f;

    for (int i = tid; i < N_QUADS; i += stride) {
        int4 c01 = __ldcs(&coord_idx4[2 * i + 0]);
        int4 c23 = __ldcs(&coord_idx4[2 * i + 1]);
        float4 B = __ldcs((const float4*)bcoef + i);

        unsigned int o0 = ((unsigned int)c01.x << 12) | (unsigned int)c01.y;
        unsigned int o1 = ((unsigned int)c01.z << 12) | (unsigned int)c01.w;
        unsigned int o2 = ((unsigned int)c23.x << 12) | (unsigned int)c23.y;
        unsigned int o3 = ((unsigned int)c23.z << 12) | (unsigned int)c23.w;

        unsigned int k0 = __ldg(&g_dcode[o0]);
        unsigned int k1 = __ldg(&g_dcode[o1]);
        unsigned int k2 = __ldg(&g_dcode[o2]);
        unsigned int k3 = __ldg(&g_dcode[o3]);

        do_pair(k0, B.x, o0, vector_mat, rep, c01.x, c01.y, esum);
        do_pair(k1, B.y, o1, vector_mat, rep, c01.z, c01.w, esum);
        do_pair(k2, B.z, o2, vector_mat, rep, c23.x, c23.y, esum);
        do_pair(k3, B.w, o3, vector_mat, rep, c23.z, c23.w, esum);
    }

    // Energy: warp reduce -> block reduce -> one atomic per block.
    #pragma unroll
    for (int o = 16; o > 0; o >>= 1)
        esum += __shfl_xor_sync(0xffffffffu, esum, o);

    __shared__ float warp_s[PAIR_THREADS / 32];
    int lane = threadIdx.x & 31;
    int wid  = threadIdx.x >> 5;
    if (lane == 0) warp_s[wid] = esum;
    __syncthreads();
    if (wid == 0) {
        float v = (lane < (PAIR_THREADS / 32)) ? warp_s[lane] : 0.0f;
        #pragma unroll
        for (int o = 16; o > 0; o >>= 1)
            v += __shfl_xor_sync(0xffffffffu, v, o);
        if (lane == 0) atomicAdd(&g_energy, v);
    }
}

// ---------- 3) fold replicas, emit output, re-zero for next replay ----------
__global__ void __launch_bounds__(256) reduce_kernel(const float* __restrict__ forces_in,
                                                     float* __restrict__ d_out) {
    int idx = blockIdx.x * blockDim.x + threadIdx.x;   // 0 .. 4*N_ATOMS-1
    int a  = idx >> 2;
    int rs = idx & 3;

    float fx = 0.0f, fy = 0.0f, fz = 0.0f;
    #pragma unroll
    for (int k = 0; k < R_REP / 4; k++) {
        int r = rs + k * 4;
        float4* p = reinterpret_cast<float4*>(g_scratch + ((size_t)r * N_ATOMS + a) * 4);
        const float4 v = *p;
        fx += v.x; fy += v.y; fz += v.z;
        *p = make_float4(0.0f, 0.0f, 0.0f, 0.0f);
    }

    fx += __shfl_xor_sync(0xffffffffu, fx, 1);
    fy += __shfl_xor_sync(0xffffffffu, fy, 1);
    fz += __shfl_xor_sync(0xffffffffu, fz, 1);
    fx += __shfl_xor_sync(0xffffffffu, fx, 2);
    fy += __shfl_xor_sync(0xffffffffu, fy, 2);
    fz += __shfl_xor_sync(0xffffffffu, fz, 2);

    if (rs == 0) {
        d_out[1 + a * 3 + 0] = forces_in[a * 3 + 0] + fx;
        d_out[1 + a * 3 + 1] = forces_in[a * 3 + 1] + fy;
        d_out[1 + a * 3 + 2] = forces_in[a * 3 + 2] + fz;
    }
    if (idx == 0) {
        d_out[0] = g_energy;
        g_energy = 0.0f;
    }
}

extern "C" void kernel_launch(void* const* d_in, const int* in_sizes, int n_in,
                              void* d_out, int out_size) {
    const float4* dist4      = (const float4*)d_in[0];  // (4096, 4096) f32
    const float*  vector_mat = (const float*)d_in[1];   // (4096, 4096, 3) f32
    const float*  forces_in  = (const float*)d_in[2];   // (4096, 3) f32 zeros
    const float*  bcoef      = (const float*)d_in[3];   // (N_PAIRS,) f32
    const int4*   coord_idx4 = (const int4*)d_in[4];    // (N_PAIRS, 2) i32

    float* out = (float*)d_out;                         // [energy, forces(4096*3)]

    convert_kernel<<<1184, 256>>>(dist4);
    pair_kernel   <<<PAIR_BLOCKS, PAIR_THREADS>>>(vector_mat, bcoef, coord_idx4);
    reduce_kernel <<<(4 * N_ATOMS) / 256, 256>>>(forces_in, out);
}

// round 17
// speedup vs baseline: 1.0704x; 1.0021x over previous
#include <cuda_runtime.h>

#define N_ATOMS 4096
#define N_PAIRS 4000000
#define N_CELLS (N_ATOMS * N_ATOMS)
#define R_REP 16
#define PAIR_THREADS 256
#define PAIR_BLOCKS 1184
#define N_QUADS (N_PAIRS / 4)
#define CUT_CODE 5462u   // code >= 5462  <=>  inv_d >= 1/12  <=>  d <= 12

// Persistent __device__ scratch (static; zero at module load).
__device__ float          g_scratch[R_REP * N_ATOMS * 4]; // replicated force accum (~1 MB)
__device__ float          g_energy;
__device__ unsigned short g_dcode[N_CELLS];               // u16 inv-codes (32 MB, L2-resident)

// ---------- 1) quantize dist -> u16 inv-codes (streaming, ~96 MB) ----------
// 8 elements per iteration: 2x float4 load (32B), 1x uint4 store (16B).
__global__ void __launch_bounds__(256) convert_kernel(const float4* __restrict__ dist4) {
    int tid = blockIdx.x * blockDim.x + threadIdx.x;
    int stride = gridDim.x * blockDim.x;
    uint4* dst = reinterpret_cast<uint4*>(g_dcode);
    const int n8 = N_CELLS / 8;
    for (int i = tid; i < n8; i += stride) {
        float4 v0 = __ldcs(&dist4[2 * i + 0]);
        float4 v1 = __ldcs(&dist4[2 * i + 1]);
        unsigned int c0 = __float2uint_rn(__fdividef(65535.0f, v0.x));
        unsigned int c1 = __float2uint_rn(__fdividef(65535.0f, v0.y));
        unsigned int c2 = __float2uint_rn(__fdividef(65535.0f, v0.z));
        unsigned int c3 = __float2uint_rn(__fdividef(65535.0f, v0.w));
        unsigned int c4 = __float2uint_rn(__fdividef(65535.0f, v1.x));
        unsigned int c5 = __float2uint_rn(__fdividef(65535.0f, v1.y));
        unsigned int c6 = __float2uint_rn(__fdividef(65535.0f, v1.z));
        unsigned int c7 = __float2uint_rn(__fdividef(65535.0f, v1.w));
        uint4 w;
        w.x = c0 | (c1 << 16);
        w.y = c2 | (c3 << 16);
        w.z = c4 | (c5 << 16);
        w.w = c6 | (c7 << 16);
        __stcs(&dst[i], w);
    }
}

__device__ __forceinline__ void do_pair(unsigned int code, float B, unsigned int ofs,
                                        const float* __restrict__ vector_mat,
                                        float* __restrict__ rep,
                                        int a, int b, float& esum) {
    if (code >= CUT_CODE) {
        float inv  = (float)code * (1.0f / 65535.0f);
        float inv2 = inv * inv;
        float inv6 = inv2 * inv2 * inv2;
        float e = B * inv6;
        esum += e;
        float f = -6.0f * e * inv;

        // 12B vec read via one aligned 16B evict-first load (50% of offsets),
        // else one extra small load. Evict-first protects the L2-resident codes.
        unsigned int byte = ofs * 12u;
        const char* base = (const char*)vector_mat + (byte & ~15u);
        float4 q = __ldcs((const float4*)base);
        unsigned int o = byte & 15u;
        float vx, vy, vz;
        if (o == 0u)      { vx = q.x; vy = q.y; vz = q.z; }
        else if (o == 4u) { vx = q.y; vy = q.z; vz = q.w; }
        else if (o == 8u) {
            vx = q.z; vy = q.w;
            vz = __ldcs((const float*)(base + 16));
        } else {            // o == 12
            float2 t = __ldcs((const float2*)(base + 16));
            vx = q.w; vy = t.x; vz = t.y;
        }

        float fx = f * vx, fy = f * vy, fz = f * vz;

        float* pa = rep + a * 4;
        float* pb = rep + b * 4;
        asm volatile("red.global.add.v4.f32 [%0], {%1,%2,%3,%4};"
                     :: "l"(pa), "f"(fx), "f"(fy), "f"(fz), "f"(0.0f) : "memory");
        asm volatile("red.global.add.v4.f32 [%0], {%1,%2,%3,%4};"
                     :: "l"(pb), "f"(-fx), "f"(-fy), "f"(-fz), "f"(0.0f) : "memory");
    }
}

// ---------- 2) pair pass: u16 code gathers (L2-resident) + vec gathers ----------
__global__ void __launch_bounds__(PAIR_THREADS) pair_kernel(
    const float* __restrict__ vector_mat,
    const float* __restrict__ bcoef,
    const int4*  __restrict__ coord_idx4)   // 2 pairs per int4
{
    int tid = blockIdx.x * blockDim.x + threadIdx.x;
    int stride = gridDim.x * blockDim.x;
    float* rep = g_scratch + (size_t)(blockIdx.x % R_REP) * (N_ATOMS * 4);

    float esum = 0.0f;

    for (int i = tid; i < N_QUADS; i += stride) {
        int4 c01 = __ldcs(&coord_idx4[2 * i + 0]);
        int4 c23 = __ldcs(&coord_idx4[2 * i + 1]);
        float4 B = __ldcs((const float4*)bcoef + i);

        unsigned int o0 = ((unsigned int)c01.x << 12) | (unsigned int)c01.y;
        unsigned int o1 = ((unsigned int)c01.z << 12) | (unsigned int)c01.w;
        unsigned int o2 = ((unsigned int)c23.x << 12) | (unsigned int)c23.y;
        unsigned int o3 = ((unsigned int)c23.z << 12) | (unsigned int)c23.w;

        unsigned int k0 = __ldg(&g_dcode[o0]);
        unsigned int k1 = __ldg(&g_dcode[o1]);
        unsigned int k2 = __ldg(&g_dcode[o2]);
        unsigned int k3 = __ldg(&g_dcode[o3]);

        do_pair(k0, B.x, o0, vector_mat, rep, c01.x, c01.y, esum);
        do_pair(k1, B.y, o1, vector_mat, rep, c01.z, c01.w, esum);
        do_pair(k2, B.z, o2, vector_mat, rep, c23.x, c23.y, esum);
        do_pair(k3, B.w, o3, vector_mat, rep, c23.z, c23.w, esum);
    }

    // Energy: warp reduce -> block reduce -> one atomic per block.
    #pragma unroll
    for (int o = 16; o > 0; o >>= 1)
        esum += __shfl_xor_sync(0xffffffffu, esum, o);

    __shared__ float warp_s[PAIR_THREADS / 32];
    int lane = threadIdx.x & 31;
    int wid  = threadIdx.x >> 5;
    if (lane == 0) warp_s[wid] = esum;
    __syncthreads();
    if (wid == 0) {
        float v = (lane < (PAIR_THREADS / 32)) ? warp_s[lane] : 0.0f;
        #pragma unroll
        for (int o = 16; o > 0; o >>= 1)
            v += __shfl_xor_sync(0xffffffffu, v, o);
        if (lane == 0) atomicAdd(&g_energy, v);
    }
}

// ---------- 3) fold replicas, emit output, re-zero for next replay ----------
__global__ void __launch_bounds__(256) reduce_kernel(const float* __restrict__ forces_in,
                                                     float* __restrict__ d_out) {
    int idx = blockIdx.x * blockDim.x + threadIdx.x;   // 0 .. 4*N_ATOMS-1
    int a  = idx >> 2;
    int rs = idx & 3;

    float fx = 0.0f, fy = 0.0f, fz = 0.0f;
    #pragma unroll
    for (int k = 0; k < R_REP / 4; k++) {
        int r = rs + k * 4;
        float4* p = reinterpret_cast<float4*>(g_scratch + ((size_t)r * N_ATOMS + a) * 4);
        const float4 v = *p;
        fx += v.x; fy += v.y; fz += v.z;
        *p = make_float4(0.0f, 0.0f, 0.0f, 0.0f);
    }

    fx += __shfl_xor_sync(0xffffffffu, fx, 1);
    fy += __shfl_xor_sync(0xffffffffu, fy, 1);
    fz += __shfl_xor_sync(0xffffffffu, fz, 1);
    fx += __shfl_xor_sync(0xffffffffu, fx, 2);
    fy += __shfl_xor_sync(0xffffffffu, fy, 2);
    fz += __shfl_xor_sync(0xffffffffu, fz, 2);

    if (rs == 0) {
        d_out[1 + a * 3 + 0] = forces_in[a * 3 + 0] + fx;
        d_out[1 + a * 3 + 1] = forces_in[a * 3 + 1] + fy;
        d_out[1 + a * 3 + 2] = forces_in[a * 3 + 2] + fz;
    }
    if (idx == 0) {
        d_out[0] = g_energy;
        g_energy = 0.0f;
    }
}

extern "C" void kernel_launch(void* const* d_in, const int* in_sizes, int n_in,
                              void* d_out, int out_size) {
    const float4* dist4      = (const float4*)d_in[0];  // (4096, 4096) f32
    const float*  vector_mat = (const float*)d_in[1];   // (4096, 4096, 3) f32
    const float*  forces_in  = (const float*)d_in[2];   // (4096, 3) f32 zeros
    const float*  bcoef      = (const float*)d_in[3];   // (N_PAIRS,) f32
    const int4*   coord_idx4 = (const int4*)d_in[4];    // (N_PAIRS, 2) i32

    float* out = (float*)d_out;                         // [energy, forces(4096*3)]

    convert_kernel<<<1184, 256>>>(dist4);
    pair_kernel   <<<PAIR_BLOCKS, PAIR_THREADS>>>(vector_mat, bcoef, coord_idx4);
    reduce_kernel <<<(4 * N_ATOMS) / 256, 256>>>(forces_in, out);
}